// round 3
// baseline (speedup 1.0000x reference)
#include <cuda_runtime.h>
#include <math_constants.h>

// Problem constants
#define B_ 8
#define T_ 4096
#define D_ 512
#define NTOK (B_ * T_)      // 32768
#define TPB 256             // threads per block; each thread owns 2 d-indices
#define GRID 296            // 148 SMs * 2 blocks

typedef unsigned long long u64;

__device__ __forceinline__ u64 pack2(float lo, float hi) {
    u64 r; asm("mov.b64 %0, {%1, %2};" : "=l"(r) : "f"(lo), "f"(hi)); return r;
}
__device__ __forceinline__ void unpack2(u64 v, float& lo, float& hi) {
    asm("mov.b64 {%0, %1}, %2;" : "=f"(lo), "=f"(hi) : "l"(v));
}
__device__ __forceinline__ void fma2(u64& d, u64 a, u64 b) {
    asm("fma.rn.f32x2 %0, %1, %2, %0;" : "+l"(d) : "l"(a), "l"(b));
}

__global__ void __launch_bounds__(TPB, 2)
router_kernel(const float* __restrict__ m0, const float* __restrict__ m1,
              const float* __restrict__ m2, const float* __restrict__ m3,
              const float* __restrict__ Wtop, const float* __restrict__ btop,
              const float* __restrict__ Wsoft, const float* __restrict__ bsoft,
              const float* __restrict__ alpha, float* __restrict__ out)
{
    __shared__ float s_part[8][TPB];       // partial sums: [logit_j][thread]
    __shared__ __align__(16) float s_red[8];

    const int t = threadIdx.x;

    // ---- One-time setup: weights for this thread's (d0,d1)=(2t,2t+1) slice,
    //      pre-packed as f32x2 pairs (lo=d0 term, hi=d1 term). ----
    // W row j, element d*4+k.  Row j as float4: index j*512 + 2t gives k=0..3 at d0,
    // j*512 + 2t + 1 gives k=0..3 at d1.
    u64 w[8][4];
    {
        const float4* Wt4 = (const float4*)Wtop;
        const float4* Ws4 = (const float4*)Wsoft;
        #pragma unroll
        for (int j = 0; j < 4; j++) {
            float4 a0 = Wt4[j * 512 + 2 * t];
            float4 a1 = Wt4[j * 512 + 2 * t + 1];
            w[j][0] = pack2(a0.x, a1.x);
            w[j][1] = pack2(a0.y, a1.y);
            w[j][2] = pack2(a0.z, a1.z);
            w[j][3] = pack2(a0.w, a1.w);
            float4 b0 = Ws4[j * 512 + 2 * t];
            float4 b1 = Ws4[j * 512 + 2 * t + 1];
            w[4 + j][0] = pack2(b0.x, b1.x);
            w[4 + j][1] = pack2(b0.y, b1.y);
            w[4 + j][2] = pack2(b0.z, b1.z);
            w[4 + j][3] = pack2(b0.w, b1.w);
        }
    }
    const float bT0 = btop[0], bT1 = btop[1], bT2 = btop[2], bT3 = btop[3];
    const float bS0 = bsoft[0], bS1 = bsoft[1], bS2 = bsoft[2], bS3 = bsoft[3];
    float aSig;
    {
        float al = alpha[0];
        aSig = 1.0f / (1.0f + __expf(-al));
    }
    const float aInv = 1.0f - aSig;

    const float2* p0 = (const float2*)m0;
    const float2* p1 = (const float2*)m1;
    const float2* p2 = (const float2*)m2;
    const float2* p3 = (const float2*)m3;
    float2* po = (float2*)out;

    int tok = blockIdx.x;
    const int stride = gridDim.x;

    // Preload first token's m-values (float2 per matrix).
    float2 c0 = make_float2(0.f, 0.f), c1 = c0, c2 = c0, c3 = c0;
    if (tok < NTOK) {
        int base = tok * (D_ / 2) + t;
        c0 = p0[base]; c1 = p1[base]; c2 = p2[base]; c3 = p3[base];
    }

    for (; tok < NTOK; tok += stride) {
        // ---- Prefetch next token (overlaps reduce/routing with DRAM latency) ----
        int ntok = tok + stride;
        float2 n0 = make_float2(0.f, 0.f), n1 = n0, n2 = n0, n3 = n0;
        if (ntok < NTOK) {
            int nbase = ntok * (D_ / 2) + t;
            n0 = p0[nbase]; n1 = p1[nbase]; n2 = p2[nbase]; n3 = p3[nbase];
        }

        // ---- GEMV partials: 8 logits, packed f32x2 over (d0,d1) ----
        u64 mm[4];
        mm[0] = pack2(c0.x, c0.y);
        mm[1] = pack2(c1.x, c1.y);
        mm[2] = pack2(c2.x, c2.y);
        mm[3] = pack2(c3.x, c3.y);

        u64 acc[8];
        #pragma unroll
        for (int j = 0; j < 8; j++) acc[j] = 0ull;
        #pragma unroll
        for (int k = 0; k < 4; k++) {
            #pragma unroll
            for (int j = 0; j < 8; j++) fma2(acc[j], mm[k], w[j][k]);
        }
        #pragma unroll
        for (int j = 0; j < 8; j++) {
            float lo, hi;
            unpack2(acc[j], lo, hi);
            s_part[j][t] = lo + hi;
        }
        __syncthreads();

        // ---- Block reduce: warp j reduces row j (256 values) ----
        {
            const int wid = t >> 5;
            const int lane = t & 31;
            float s = 0.f;
            #pragma unroll
            for (int i = 0; i < 8; i++) s += s_part[wid][lane + 32 * i];
            #pragma unroll
            for (int off = 16; off > 0; off >>= 1)
                s += __shfl_xor_sync(0xffffffffu, s, off);
            if (lane == 0) s_red[wid] = s;
        }
        __syncthreads();

        // ---- Routing math (redundant per thread; cheap) ----
        float T0 = s_red[0] + bT0, T1 = s_red[1] + bT1;
        float T2 = s_red[2] + bT2, T3 = s_red[3] + bT3;
        float S0 = s_red[4] + bS0, S1 = s_red[5] + bS1;
        float S2 = s_red[6] + bS2, S3 = s_red[7] + bS3;

        // soft = softmax(S)
        float ms = fmaxf(fmaxf(S0, S1), fmaxf(S2, S3));
        float e0 = __expf(S0 - ms), e1 = __expf(S1 - ms);
        float e2 = __expf(S2 - ms), e3 = __expf(S3 - ms);
        float inv = 1.0f / (e0 + e1 + e2 + e3);

        // hard = scatter(softmax(top2(T)))  (stable argmax: first occurrence wins)
        float Tv[4] = {T0, T1, T2, T3};
        int i1 = 0; float v1 = Tv[0];
        #pragma unroll
        for (int k = 1; k < 4; k++) if (Tv[k] > v1) { v1 = Tv[k]; i1 = k; }
        int i2 = -1; float v2 = -CUDART_INF_F;
        #pragma unroll
        for (int k = 0; k < 4; k++) if (k != i1 && Tv[k] > v2) { v2 = Tv[k]; i2 = k; }
        float pp1 = 1.0f / (1.0f + __expf(v2 - v1));   // softmax([v1,v2])[0]
        float pp2 = 1.0f - pp1;

        float wk[4];
        float ee[4] = {e0, e1, e2, e3};
        #pragma unroll
        for (int k = 0; k < 4; k++) {
            float hard = (k == i1) ? pp1 : ((k == i2) ? pp2 : 0.0f);
            wk[k] = fmaf(aSig, hard, aInv * (ee[k] * inv));
        }

        // ---- Output: out[d] = sum_k m_k[d] * w_k ----
        float2 o;
        o.x = c0.x * wk[0] + c1.x * wk[1] + c2.x * wk[2] + c3.x * wk[3];
        o.y = c0.y * wk[0] + c1.y * wk[1] + c2.y * wk[2] + c3.y * wk[3];
        po[tok * (D_ / 2) + t] = o;

        c0 = n0; c1 = n1; c2 = n2; c3 = n3;
    }
}

extern "C" void kernel_launch(void* const* d_in, const int* in_sizes, int n_in,
                              void* d_out, int out_size) {
    (void)in_sizes; (void)n_in; (void)out_size;
    router_kernel<<<GRID, TPB>>>(
        (const float*)d_in[0], (const float*)d_in[1],
        (const float*)d_in[2], (const float*)d_in[3],
        (const float*)d_in[4], (const float*)d_in[5],
        (const float*)d_in[6], (const float*)d_in[7],
        (const float*)d_in[8], (float*)d_out);
}

// round 4
// speedup vs baseline: 1.0817x; 1.0817x over previous
#include <cuda_runtime.h>
#include <math_constants.h>

// Problem constants
#define B_ 8
#define T_ 4096
#define D_ 512
#define NTOK (B_ * T_)      // 32768
#define TPB 256             // threads per block; each thread owns 2 d-indices
#define GRID 296            // 148 SMs * 2 blocks
#define TPI 4               // tokens per iteration

typedef unsigned long long u64;

__device__ __forceinline__ u64 pack2(float lo, float hi) {
    u64 r; asm("mov.b64 %0, {%1, %2};" : "=l"(r) : "f"(lo), "f"(hi)); return r;
}
__device__ __forceinline__ void unpack2(u64 v, float& lo, float& hi) {
    asm("mov.b64 {%0, %1}, %2;" : "=f"(lo), "=f"(hi) : "l"(v));
}
__device__ __forceinline__ void fma2(u64& d, u64 a, u64 b) {
    asm("fma.rn.f32x2 %0, %1, %2, %0;" : "+l"(d) : "l"(a), "l"(b));
}

__global__ void __launch_bounds__(TPB, 2)
router_kernel(const float* __restrict__ m0, const float* __restrict__ m1,
              const float* __restrict__ m2, const float* __restrict__ m3,
              const float* __restrict__ Wtop, const float* __restrict__ btop,
              const float* __restrict__ Wsoft, const float* __restrict__ bsoft,
              const float* __restrict__ alpha, float* __restrict__ out)
{
    // Packed partial sums: [token][logit-pair][thread], pair p = logits (2p, 2p+1)
    __shared__ u64 s_part[TPI][4][TPB];          // 32 KB
    __shared__ float s_red[TPI][8];

    const int t = threadIdx.x;

    // ---- One-time: weights for this thread's (d0,d1)=(2t,2t+1), packed f32x2 ----
    u64 w[8][4];
    {
        const float4* Wt4 = (const float4*)Wtop;
        const float4* Ws4 = (const float4*)Wsoft;
        #pragma unroll
        for (int j = 0; j < 4; j++) {
            float4 a0 = Wt4[j * 512 + 2 * t];
            float4 a1 = Wt4[j * 512 + 2 * t + 1];
            w[j][0] = pack2(a0.x, a1.x);
            w[j][1] = pack2(a0.y, a1.y);
            w[j][2] = pack2(a0.z, a1.z);
            w[j][3] = pack2(a0.w, a1.w);
            float4 b0 = Ws4[j * 512 + 2 * t];
            float4 b1 = Ws4[j * 512 + 2 * t + 1];
            w[4 + j][0] = pack2(b0.x, b1.x);
            w[4 + j][1] = pack2(b0.y, b1.y);
            w[4 + j][2] = pack2(b0.z, b1.z);
            w[4 + j][3] = pack2(b0.w, b1.w);
        }
    }
    const float bT0 = btop[0], bT1 = btop[1], bT2 = btop[2], bT3 = btop[3];
    const float bS0 = bsoft[0], bS1 = bsoft[1], bS2 = bsoft[2], bS3 = bsoft[3];
    const float aSig = 1.0f / (1.0f + __expf(-alpha[0]));
    const float aInv = 1.0f - aSig;

    // m-data as packed u64 (lo = even d, hi = odd d) — same bits as float2.
    const u64* q0 = (const u64*)m0;
    const u64* q1 = (const u64*)m1;
    const u64* q2 = (const u64*)m2;
    const u64* q3 = (const u64*)m3;
    u64* qo = (u64*)out;

    const int wid = t >> 5;
    const int lane = t & 31;

    for (int tok0 = blockIdx.x * TPI; tok0 < NTOK; tok0 += GRID * TPI) {
        // ---- Batched loads: 16 independent LDG.64 (MLP=16) ----
        u64 dm[TPI][4];
        #pragma unroll
        for (int i = 0; i < TPI; i++) {
            int base = (tok0 + i) * (D_ / 2) + t;
            dm[i][0] = q0[base];
            dm[i][1] = q1[base];
            dm[i][2] = q2[base];
            dm[i][3] = q3[base];
        }

        // ---- GEMV partials for all 4 tokens, packed STS.64 ----
        #pragma unroll
        for (int i = 0; i < TPI; i++) {
            u64 acc[8];
            #pragma unroll
            for (int j = 0; j < 8; j++) acc[j] = 0ull;
            #pragma unroll
            for (int k = 0; k < 4; k++) {
                #pragma unroll
                for (int j = 0; j < 8; j++) fma2(acc[j], dm[i][k], w[j][k]);
            }
            #pragma unroll
            for (int p = 0; p < 4; p++) {
                float a0, a1, b0, b1;
                unpack2(acc[2 * p],     a0, a1);
                unpack2(acc[2 * p + 1], b0, b1);
                s_part[i][p][t] = pack2(a0 + a1, b0 + b1);
            }
        }
        __syncthreads();

        // ---- Reduce: 16 rows (token i, pair p); each of 8 warps does 2 ----
        #pragma unroll
        for (int r = 0; r < 2; r++) {
            int row = wid + 8 * r;        // 0..15
            int i = row >> 2, p = row & 3;
            float slo = 0.f, shi = 0.f;
            #pragma unroll
            for (int c = 0; c < 8; c++) {
                float lo, hi;
                unpack2(s_part[i][p][lane + 32 * c], lo, hi);
                slo += lo; shi += hi;
            }
            #pragma unroll
            for (int off = 16; off > 0; off >>= 1) {
                slo += __shfl_xor_sync(0xffffffffu, slo, off);
                shi += __shfl_xor_sync(0xffffffffu, shi, off);
            }
            if (lane == 0) {
                s_red[i][2 * p]     = slo;
                s_red[i][2 * p + 1] = shi;
            }
        }
        __syncthreads();

        // ---- Routing + epilogue per token (routing redundant per thread) ----
        #pragma unroll
        for (int i = 0; i < TPI; i++) {
            float T0 = s_red[i][0] + bT0, T1 = s_red[i][1] + bT1;
            float T2 = s_red[i][2] + bT2, T3 = s_red[i][3] + bT3;
            float S0 = s_red[i][4] + bS0, S1 = s_red[i][5] + bS1;
            float S2 = s_red[i][6] + bS2, S3 = s_red[i][7] + bS3;

            // soft = softmax(S)
            float ms = fmaxf(fmaxf(S0, S1), fmaxf(S2, S3));
            float e0 = __expf(S0 - ms), e1 = __expf(S1 - ms);
            float e2 = __expf(S2 - ms), e3 = __expf(S3 - ms);
            float inv = 1.0f / (e0 + e1 + e2 + e3);

            // hard = scatter(softmax(top2(T))); first-occurrence argmax (lax.top_k tie rule)
            float Tv[4] = {T0, T1, T2, T3};
            int i1 = 0; float v1 = Tv[0];
            #pragma unroll
            for (int k = 1; k < 4; k++) if (Tv[k] > v1) { v1 = Tv[k]; i1 = k; }
            int i2 = -1; float v2 = -CUDART_INF_F;
            #pragma unroll
            for (int k = 0; k < 4; k++) if (k != i1 && Tv[k] > v2) { v2 = Tv[k]; i2 = k; }
            float pp1 = 1.0f / (1.0f + __expf(v2 - v1));
            float pp2 = 1.0f - pp1;

            float ee[4] = {e0, e1, e2, e3};
            u64 o = 0ull;
            #pragma unroll
            for (int k = 0; k < 4; k++) {
                float hard = (k == i1) ? pp1 : ((k == i2) ? pp2 : 0.0f);
                float wk = fmaf(aSig, hard, aInv * (ee[k] * inv));
                fma2(o, dm[i][k], pack2(wk, wk));
            }
            qo[(tok0 + i) * (D_ / 2) + t] = o;
        }
    }
}

extern "C" void kernel_launch(void* const* d_in, const int* in_sizes, int n_in,
                              void* d_out, int out_size) {
    (void)in_sizes; (void)n_in; (void)out_size;
    router_kernel<<<GRID, TPB>>>(
        (const float*)d_in[0], (const float*)d_in[1],
        (const float*)d_in[2], (const float*)d_in[3],
        (const float*)d_in[4], (const float*)d_in[5],
        (const float*)d_in[6], (const float*)d_in[7],
        (const float*)d_in[8], (float*)d_out);
}

// round 5
// speedup vs baseline: 1.3782x; 1.2741x over previous
#include <cuda_runtime.h>
#include <math_constants.h>

// Problem constants
#define B_ 8
#define T_ 4096
#define D_ 512
#define NTOK (B_ * T_)      // 32768
#define TPB 256             // threads per block; each thread owns 2 d-indices
#define GRID 296            // 148 SMs * 2 blocks
#define TPI 4               // tokens per iteration

typedef unsigned long long u64;

__device__ __forceinline__ u64 pack2(float lo, float hi) {
    u64 r; asm("mov.b64 %0, {%1, %2};" : "=l"(r) : "f"(lo), "f"(hi)); return r;
}
__device__ __forceinline__ void unpack2(u64 v, float& lo, float& hi) {
    asm("mov.b64 {%0, %1}, %2;" : "=f"(lo), "=f"(hi) : "l"(v));
}
__device__ __forceinline__ void fma2(u64& d, u64 a, u64 b) {
    asm("fma.rn.f32x2 %0, %1, %2, %0;" : "+l"(d) : "l"(a), "l"(b));
}
__device__ __forceinline__ u64 add2(u64 a, u64 b) {
    u64 r; asm("add.rn.f32x2 %0, %1, %2;" : "=l"(r) : "l"(a), "l"(b)); return r;
}
__device__ __forceinline__ u64 shfl_xor_u64(u64 v, int off) {
    float lo, hi; unpack2(v, lo, hi);
    lo = __shfl_xor_sync(0xffffffffu, lo, off);
    hi = __shfl_xor_sync(0xffffffffu, hi, off);
    return pack2(lo, hi);
}

__global__ void __launch_bounds__(TPB, 2)
router_kernel(const float* __restrict__ m0, const float* __restrict__ m1,
              const float* __restrict__ m2, const float* __restrict__ m3,
              const float* __restrict__ Wtop, const float* __restrict__ btop,
              const float* __restrict__ Wsoft, const float* __restrict__ bsoft,
              const float* __restrict__ alpha, float* __restrict__ out)
{
    // Packed partials: [token][logit-pair p][thread]; pair p holds logits (2p,2p+1)
    __shared__ u64 s_part[TPI][4][TPB];               // 32 KB
    __shared__ __align__(16) u64 s_wk[TPI][2];        // per-token final weights (wk0,wk1),(wk2,wk3)

    const int t = threadIdx.x;
    const int wid = t >> 5;
    const int lane = t & 31;

    // ---- One-time: weights for this thread's (d0,d1)=(2t,2t+1), packed f32x2 ----
    u64 w[8][4];
    {
        const float4* Wt4 = (const float4*)Wtop;
        const float4* Ws4 = (const float4*)Wsoft;
        #pragma unroll
        for (int j = 0; j < 4; j++) {
            float4 a0 = Wt4[j * 512 + 2 * t];
            float4 a1 = Wt4[j * 512 + 2 * t + 1];
            w[j][0] = pack2(a0.x, a1.x);
            w[j][1] = pack2(a0.y, a1.y);
            w[j][2] = pack2(a0.z, a1.z);
            w[j][3] = pack2(a0.w, a1.w);
            float4 b0 = Ws4[j * 512 + 2 * t];
            float4 b1 = Ws4[j * 512 + 2 * t + 1];
            w[4 + j][0] = pack2(b0.x, b1.x);
            w[4 + j][1] = pack2(b0.y, b1.y);
            w[4 + j][2] = pack2(b0.z, b1.z);
            w[4 + j][3] = pack2(b0.w, b1.w);
        }
    }
    const float aSig = 1.0f / (1.0f + __expf(-alpha[0]));
    const float aInv = 1.0f - aSig;

    const u64* q0 = (const u64*)m0;
    const u64* q1 = (const u64*)m1;
    const u64* q2 = (const u64*)m2;
    const u64* q3 = (const u64*)m3;
    u64* qo = (u64*)out;

    for (int tok0 = blockIdx.x * TPI; tok0 < NTOK; tok0 += GRID * TPI) {
        const bool full = (tok0 + TPI) <= NTOK;

        // ---- Batched loads: up to 16 independent LDG.64 ----
        u64 dm[TPI][4];
        #pragma unroll
        for (int i = 0; i < TPI; i++) {
            int base = (tok0 + i) * (D_ / 2) + t;
            if (full || (tok0 + i) < NTOK) {
                dm[i][0] = q0[base];
                dm[i][1] = q1[base];
                dm[i][2] = q2[base];
                dm[i][3] = q3[base];
            } else {
                dm[i][0] = dm[i][1] = dm[i][2] = dm[i][3] = 0ull;
            }
        }

        // ---- GEMV partials for all tokens, packed STS.64 ----
        #pragma unroll
        for (int i = 0; i < TPI; i++) {
            u64 acc[8];
            #pragma unroll
            for (int j = 0; j < 8; j++) acc[j] = 0ull;
            #pragma unroll
            for (int k = 0; k < 4; k++) {
                #pragma unroll
                for (int j = 0; j < 8; j++) fma2(acc[j], dm[i][k], w[j][k]);
            }
            #pragma unroll
            for (int p = 0; p < 4; p++) {
                float a0, a1, b0, b1;
                unpack2(acc[2 * p],     a0, a1);   // logit 2p  : (d0,d1) parts
                unpack2(acc[2 * p + 1], b0, b1);   // logit 2p+1: (d0,d1) parts
                s_part[i][p][t] = pack2(a0 + a1, b0 + b1);
            }
        }
        __syncthreads();

        // ---- Token-per-warp reduce + routing: warp w owns token w ----
        if (wid < TPI) {
            u64 accp[4];
            #pragma unroll
            for (int p = 0; p < 4; p++) {
                const ulonglong2* row = (const ulonglong2*)&s_part[wid][p][0]; // 128 x 16B
                ulonglong2 x0 = row[lane];
                ulonglong2 x1 = row[lane + 32];
                ulonglong2 x2 = row[lane + 64];
                ulonglong2 x3 = row[lane + 96];
                accp[p] = add2(add2(add2(x0.x, x0.y), add2(x1.x, x1.y)),
                               add2(add2(x2.x, x2.y), add2(x3.x, x3.y)));
            }
            #pragma unroll
            for (int off = 16; off > 0; off >>= 1) {
                #pragma unroll
                for (int p = 0; p < 4; p++)
                    accp[p] = add2(accp[p], shfl_xor_u64(accp[p], off));
            }

            // Routing math, once per token (all lanes redundant within this warp)
            float T0, T1, T2, T3, S0, S1, S2, S3;
            unpack2(accp[0], T0, T1);
            unpack2(accp[1], T2, T3);
            unpack2(accp[2], S0, S1);
            unpack2(accp[3], S2, S3);
            T0 += btop[0];  T1 += btop[1];  T2 += btop[2];  T3 += btop[3];
            S0 += bsoft[0]; S1 += bsoft[1]; S2 += bsoft[2]; S3 += bsoft[3];

            // soft = softmax(S)
            float ms = fmaxf(fmaxf(S0, S1), fmaxf(S2, S3));
            float e0 = __expf(S0 - ms), e1 = __expf(S1 - ms);
            float e2 = __expf(S2 - ms), e3 = __expf(S3 - ms);
            float inv = 1.0f / (e0 + e1 + e2 + e3);

            // hard = scatter(softmax(top2(T))); first-occurrence argmax (lax.top_k tie rule)
            float Tv[4] = {T0, T1, T2, T3};
            int i1 = 0; float v1 = Tv[0];
            #pragma unroll
            for (int k = 1; k < 4; k++) if (Tv[k] > v1) { v1 = Tv[k]; i1 = k; }
            int i2 = -1; float v2 = -CUDART_INF_F;
            #pragma unroll
            for (int k = 0; k < 4; k++) if (k != i1 && Tv[k] > v2) { v2 = Tv[k]; i2 = k; }
            float pp1 = 1.0f / (1.0f + __expf(v2 - v1));
            float pp2 = 1.0f - pp1;

            float ee[4] = {e0, e1, e2, e3};
            float wk[4];
            #pragma unroll
            for (int k = 0; k < 4; k++) {
                float hard = (k == i1) ? pp1 : ((k == i2) ? pp2 : 0.0f);
                wk[k] = fmaf(aSig, hard, aInv * (ee[k] * inv));
            }
            if (lane == 0) {
                s_wk[wid][0] = pack2(wk[0], wk[1]);
                s_wk[wid][1] = pack2(wk[2], wk[3]);
            }
        }
        __syncthreads();

        // ---- Epilogue: out[d] = sum_k m_k[d] * wk[k]  (1 LDS.128 + 4 FMA2 + STG)
        #pragma unroll
        for (int i = 0; i < TPI; i++) {
            if (full || (tok0 + i) < NTOK) {
                ulonglong2 wp = *(const ulonglong2*)&s_wk[i][0];
                float w0, w1, w2, w3;
                unpack2(wp.x, w0, w1);
                unpack2(wp.y, w2, w3);
                u64 o = 0ull;
                fma2(o, dm[i][0], pack2(w0, w0));
                fma2(o, dm[i][1], pack2(w1, w1));
                fma2(o, dm[i][2], pack2(w2, w2));
                fma2(o, dm[i][3], pack2(w3, w3));
                qo[(tok0 + i) * (D_ / 2) + t] = o;
            }
        }
    }
}

extern "C" void kernel_launch(void* const* d_in, const int* in_sizes, int n_in,
                              void* d_out, int out_size) {
    (void)in_sizes; (void)n_in; (void)out_size;
    router_kernel<<<GRID, TPB>>>(
        (const float*)d_in[0], (const float*)d_in[1],
        (const float*)d_in[2], (const float*)d_in[3],
        (const float*)d_in[4], (const float*)d_in[5],
        (const float*)d_in[6], (const float*)d_in[7],
        (const float*)d_in[8], (float*)d_out);
}